// round 4
// baseline (speedup 1.0000x reference)
#include <cuda_runtime.h>
#include <cuda_fp16.h>

// Problem constants (fixed shapes from reference)
#define VV 100000
#define DD 64
#define BB 4096
#define LL 50
#define KK 3
#define NBAGS (BB * (2 + KK))   // 20480
#define MAX_NORM 20.0f

// Renormed embedding table in fp16 (12.8 MB).
__device__ __half d_table[VV * DD];

// Kernel 1: renorm rows. 8 lanes per row; each lane reads 8 floats (2x float4),
// reduces norm across 8 lanes, writes 8 halves (uint4, 16 B).
__global__ __launch_bounds__(256) void renorm_kernel(const float* __restrict__ emb) {
    int idx  = blockIdx.x * blockDim.x + threadIdx.x;
    int row  = idx >> 3;
    int lane = threadIdx.x & 7;
    if (row >= VV) return;

    const float4* e4 = (const float4*)emb;
    float4 v0 = e4[row * 16 + lane * 2 + 0];
    float4 v1 = e4[row * 16 + lane * 2 + 1];

    float ss = v0.x*v0.x + v0.y*v0.y + v0.z*v0.z + v0.w*v0.w
             + v1.x*v1.x + v1.y*v1.y + v1.z*v1.z + v1.w*v1.w;
    ss += __shfl_xor_sync(0xffffffffu, ss, 1);
    ss += __shfl_xor_sync(0xffffffffu, ss, 2);
    ss += __shfl_xor_sync(0xffffffffu, ss, 4);

    float norm = sqrtf(ss);
    float s = (norm > MAX_NORM) ? (MAX_NORM / norm) : 1.0f;

    __half2 h0 = __floats2half2_rn(v0.x * s, v0.y * s);
    __half2 h1 = __floats2half2_rn(v0.z * s, v0.w * s);
    __half2 h2 = __floats2half2_rn(v1.x * s, v1.y * s);
    __half2 h3 = __floats2half2_rn(v1.z * s, v1.w * s);
    uint4 packed;
    packed.x = *reinterpret_cast<unsigned*>(&h0);
    packed.y = *reinterpret_cast<unsigned*>(&h1);
    packed.z = *reinterpret_cast<unsigned*>(&h2);
    packed.w = *reinterpret_cast<unsigned*>(&h3);
    ((uint4*)d_table)[row * 8 + lane] = packed;
}

// Kernel 2: embedding-bag sum. ONE WARP PER BAG.
// Each lane loads one u32 (2 halves) from the SAME row -> every gather is one
// perfectly-coalesced 128 B line = 1 L1tex wavefront per LDG (cross-LDG rate).
// Tokens staged through per-warp smem (2 coalesced LDGs to fill, LDS-broadcast
// in the loop) to keep the LSU at 50 gather-LDGs per bag.
// Bag order matches output tuple flatten: [l (B) | r (B) | neg (B*K)].
__global__ __launch_bounds__(256) void bag_kernel(
    const int* __restrict__ tl,
    const int* __restrict__ tr,
    const int* __restrict__ tn,
    float* __restrict__ out)
{
    __shared__ int s_tok[8][LL + 2];        // 8 warps/block, pad to dodge conflicts

    int warp = threadIdx.x >> 5;
    int lane = threadIdx.x & 31;
    int bag  = blockIdx.x * 8 + warp;
    if (bag >= NBAGS) return;

    const int* p;
    if (bag < BB)          p = tl + bag * LL;
    else if (bag < 2 * BB) p = tr + (bag - BB) * LL;
    else                   p = tn + (bag - 2 * BB) * LL;

    // Stage this bag's 50 tokens into smem (lanes 0-24 load 2 each, coalesced).
    if (lane < 25) {
        s_tok[warp][lane]      = p[lane];
        s_tok[warp][lane + 25] = p[lane + 25];
    }
    __syncwarp();

    const unsigned* t32 = (const unsigned*)d_table;   // 32 u32 per row
    float2 acc = make_float2(0.f, 0.f);

    #pragma unroll 10
    for (int t = 0; t < LL; ++t) {
        int tok = s_tok[warp][t];                     // LDS broadcast
        unsigned v = __ldg(&t32[tok * 32 + lane]);    // one 128B line per warp-LDG
        __half2 h = *reinterpret_cast<__half2*>(&v);
        float2 f = __half22float2(h);
        // packed f32x2 add: one FMA-pipe op instead of two FADDs
        asm("{\n\t"
            ".reg .b64 a, b;\n\t"
            "mov.b64 a, {%0, %1};\n\t"
            "mov.b64 b, {%2, %3};\n\t"
            "add.rn.f32x2 a, a, b;\n\t"
            "mov.b64 {%0, %1}, a;\n\t"
            "}"
            : "+f"(acc.x), "+f"(acc.y)
            : "f"(f.x), "f"(f.y));
    }

    // Lane i owns dims [2i, 2i+1]: warp writes 256 B contiguous.
    ((float2*)out)[bag * 32 + lane] = acc;
}

extern "C" void kernel_launch(void* const* d_in, const int* in_sizes, int n_in,
                              void* d_out, int out_size) {
    const float* emb = (const float*)d_in[0];
    const int*   tl  = (const int*)d_in[1];
    const int*   tr  = (const int*)d_in[2];
    const int*   tn  = (const int*)d_in[3];
    float*       out = (float*)d_out;

    int renorm_blocks = (VV * 8 + 255) / 256;    // 3125 (32 rows per block)
    renorm_kernel<<<renorm_blocks, 256>>>(emb);

    int bag_blocks = NBAGS / 8;                  // 2560 (8 bags = 8 warps per block)
    bag_kernel<<<bag_blocks, 256>>>(tl, tr, tn, out);
}

// round 5
// speedup vs baseline: 1.1218x; 1.1218x over previous
#include <cuda_runtime.h>
#include <cuda_fp16.h>

// Problem constants (fixed shapes from reference)
#define VV 100000
#define DD 64
#define BB 4096
#define LL 50
#define KK 3
#define NBAGS (BB * (2 + KK))   // 20480
#define MAX_NORM 20.0f

// Renormed embedding table in fp16 (12.8 MB).
__device__ __half d_table[VV * DD];

// Kernel 1: renorm rows. 8 lanes per row; each lane reads 8 floats (2x float4),
// reduces norm across 8 lanes, writes 8 halves (uint4, 16 B).
__global__ __launch_bounds__(256) void renorm_kernel(const float* __restrict__ emb) {
    int idx  = blockIdx.x * blockDim.x + threadIdx.x;
    int row  = idx >> 3;
    int lane = threadIdx.x & 7;
    if (row >= VV) return;

    const float4* e4 = (const float4*)emb;
    float4 v0 = e4[row * 16 + lane * 2 + 0];
    float4 v1 = e4[row * 16 + lane * 2 + 1];

    float ss = v0.x*v0.x + v0.y*v0.y + v0.z*v0.z + v0.w*v0.w
             + v1.x*v1.x + v1.y*v1.y + v1.z*v1.z + v1.w*v1.w;
    ss += __shfl_xor_sync(0xffffffffu, ss, 1);
    ss += __shfl_xor_sync(0xffffffffu, ss, 2);
    ss += __shfl_xor_sync(0xffffffffu, ss, 4);

    float norm = sqrtf(ss);
    float s = (norm > MAX_NORM) ? (MAX_NORM / norm) : 1.0f;

    __half2 h0 = __floats2half2_rn(v0.x * s, v0.y * s);
    __half2 h1 = __floats2half2_rn(v0.z * s, v0.w * s);
    __half2 h2 = __floats2half2_rn(v1.x * s, v1.y * s);
    __half2 h3 = __floats2half2_rn(v1.z * s, v1.w * s);
    uint4 packed;
    packed.x = *reinterpret_cast<unsigned*>(&h0);
    packed.y = *reinterpret_cast<unsigned*>(&h1);
    packed.z = *reinterpret_cast<unsigned*>(&h2);
    packed.w = *reinterpret_cast<unsigned*>(&h3);
    ((uint4*)d_table)[row * 8 + lane] = packed;
}

// Kernel 2: embedding-bag sum. EXACT R1 geometry (the config that saturated
// L2), fp16 payload: 16 lanes per bag, each lane loads one uint2 = 4 halves
// (8 B) per token -> 16 lanes * 8 B = 128 B = one L2 line per bag-gather,
// 2 lines per warp-LDG (2 bags per warp). Direct token loads, unroll 10.
// Bag order matches output tuple flatten: [l (B) | r (B) | neg (B*K)].
__global__ __launch_bounds__(256) void bag_kernel(
    const int* __restrict__ tl,
    const int* __restrict__ tr,
    const int* __restrict__ tn,
    float* __restrict__ out)
{
    int idx  = blockIdx.x * blockDim.x + threadIdx.x;
    int bag  = idx >> 4;
    int lane = threadIdx.x & 15;
    if (bag >= NBAGS) return;

    const int* p;
    if (bag < BB)          p = tl + bag * LL;
    else if (bag < 2 * BB) p = tr + (bag - BB) * LL;
    else                   p = tn + (bag - 2 * BB) * LL;

    const uint2* t2 = (const uint2*)d_table;   // 16 uint2 per row (64 halves)
    float4 acc = make_float4(0.f, 0.f, 0.f, 0.f);

    #pragma unroll 10
    for (int t = 0; t < LL; ++t) {
        int tok = p[t];                        // broadcast across the 16-lane group
        uint2 v = __ldg(&t2[tok * 16 + lane]);
        __half2 a = *reinterpret_cast<__half2*>(&v.x);
        __half2 b = *reinterpret_cast<__half2*>(&v.y);
        float2 fa = __half22float2(a);
        float2 fb = __half22float2(b);
        acc.x += fa.x; acc.y += fa.y;
        acc.z += fb.x; acc.w += fb.y;
    }

    // Lane i owns dims [4i, 4i+3]: warp writes 256 B contiguous per bag-half.
    ((float4*)out)[bag * 16 + lane] = acc;
}

extern "C" void kernel_launch(void* const* d_in, const int* in_sizes, int n_in,
                              void* d_out, int out_size) {
    const float* emb = (const float*)d_in[0];
    const int*   tl  = (const int*)d_in[1];
    const int*   tr  = (const int*)d_in[2];
    const int*   tn  = (const int*)d_in[3];
    float*       out = (float*)d_out;

    int renorm_blocks = (VV * 8 + 255) / 256;    // 3125 (32 rows per block)
    renorm_kernel<<<renorm_blocks, 256>>>(emb);

    int bag_blocks = NBAGS * 16 / 256;           // 1280 (16 bags per block)
    bag_kernel<<<bag_blocks, 256>>>(tl, tr, tn, out);
}